// round 9
// baseline (speedup 1.0000x reference)
#include <cuda_runtime.h>
#include <cuda_bf16.h>
#include <stdint.h>

// RZGate, L=12, D=2, J=1.  S = diag(1,-1), so U is DIAGONAL:
//   theta(row) = -0.5 * sum_i a_i * (bit_i(row) ? -1 : +1)   (site 0 = MSB)
//   out[row,b] = (cos th + i sin th) * x[row,b]   (complex64 interleaved)
//
// VALIDATED ABI (rounds 6/8 passes, rel_err 2.2e-7):
//   x = f32[1,048,576] (4096x256 row-major), angle = f32[12],
//   out = 8 MB of interleaved (re,im) float pairs.
// VALIDATED HAZARD: buffers are NOT guaranteed 8/16B-aligned (rounds 3-5
//   IMAs were misaligned vector accesses; round 8's host alignment gate
//   failed). => per-pointer runtime vector-width dispatch.

#define LQ      12
#define NROWS   4096
#define NBATCH  256
#define NELEMS  (NROWS * NBATCH)

// ---------------------------------------------------------------------------
// Main kernel: warp == row. 512 blocks x 256 threads = 4096 warps.
// Each lane: 8 consecutive elements of its row. Phase by warp shfl-reduction,
// one sincosf per row (lane 0), shfl broadcast. No smem, no syncthreads.
// xv4 / ov4 / ov2 are uniform alignment flags.
// ---------------------------------------------------------------------------
__global__ void __launch_bounds__(256)
rz_main(const float* __restrict__ x,
        const float* __restrict__ ang,
        float*       __restrict__ out,
        int xv4, int ov4, int ov2)
{
    const int lane = threadIdx.x & 31;
    const int row  = (blockIdx.x * blockDim.x + threadIdx.x) >> 5;  // 0..4095

    // --- per-row phase: lane-parallel dot(angle, sign) + butterfly reduce ---
    float term = 0.0f;
    if (lane < LQ) {
        const int bit = (row >> (LQ - 1 - lane)) & 1;
        term = ang[lane] * (bit ? -1.0f : 1.0f);
    }
#pragma unroll
    for (int o = 16; o; o >>= 1)
        term += __shfl_xor_sync(0xFFFFFFFFu, term, o);

    float cs = 0.0f, sn = 0.0f;
    if (lane == 0) sincosf(-0.5f * term, &sn, &cs);
    cs = __shfl_sync(0xFFFFFFFFu, cs, 0);
    sn = __shfl_sync(0xFFFFFFFFu, sn, 0);

    // --- stream 8 elements per lane (front-batched loads, MLP = 8) ---
    const int e0 = row * NBATCH + lane * 8;

    float v[8];
    if (xv4) {
        const float4* __restrict__ x4 = (const float4*)x;
        const float4 a = x4[(e0 >> 2) + 0];
        const float4 b = x4[(e0 >> 2) + 1];
        v[0] = a.x; v[1] = a.y; v[2] = a.z; v[3] = a.w;
        v[4] = b.x; v[5] = b.y; v[6] = b.z; v[7] = b.w;
    } else {
#pragma unroll
        for (int j = 0; j < 8; ++j) v[j] = __ldg(&x[e0 + j]);
    }

    const int f0 = 2 * e0;   // float index into out; lane-contiguous 64B span
    if (ov4) {
        float4* __restrict__ o4 = (float4*)(out + f0);
#pragma unroll
        for (int j = 0; j < 4; ++j)
            o4[j] = make_float4(cs * v[2*j],     sn * v[2*j],
                                cs * v[2*j + 1], sn * v[2*j + 1]);
    } else if (ov2) {
        float2* __restrict__ o2 = (float2*)(out + f0);
#pragma unroll
        for (int j = 0; j < 8; ++j)
            o2[j] = make_float2(cs * v[j], sn * v[j]);
    } else {
#pragma unroll
        for (int j = 0; j < 8; ++j) {
            out[f0 + 2*j]     = cs * v[j];
            out[f0 + 2*j + 1] = sn * v[j];
        }
    }
}

// ---------------------------------------------------------------------------
// Fallback: round-6-proven all-scalar, dtype-probing, bounds-clamped kernel.
// Only used if the validated ABI conditions unexpectedly don't hold.
// ---------------------------------------------------------------------------
__global__ void __launch_bounds__(256)
rz_safe(const void* __restrict__ xraw, int x_elems,
        const void* __restrict__ araw,
        float* __restrict__ outf, int n_out_floats,
        int interleaved, int x_hint, int a_hint)
{
    __shared__ float2 s_phase[4];
    __shared__ int    s_xbf;
    const int t = threadIdx.x;

    if (t == 0) {
        int xbf = x_hint;
        if (xbf < 0) {
            const unsigned short* h = (const unsigned short*)xraw;
            int match = 0;
            for (int i = 0; i < 32; ++i) {
                const int e = (h[2 * i] >> 7) & 0xFF;
                if (e >= 117 && e <= 132) ++match;
            }
            xbf = (match >= 24) ? 1 : 0;
        }
        s_xbf = xbf;
    }
    __syncthreads();
    const int xbf = s_xbf;

    if (t < 4) {
        const int abf = (a_hint >= 0) ? a_hint : xbf;
        const int row = 4 * blockIdx.x + t;
        float th = 0.0f;
#pragma unroll
        for (int i = 0; i < LQ; ++i) {
            float a;
            if (abf) a = __bfloat162float(((const __nv_bfloat16*)araw)[i]);
            else     a = ((const float*)araw)[i];
            const int bit = (row >> (LQ - 1 - i)) & 1;
            th = fmaf(a, bit ? -1.0f : 1.0f, th);
        }
        th *= -0.5f;
        float sc, cc;
        sincosf(th, &sc, &cc);
        s_phase[t] = make_float2(cc, sc);
    }
    __syncthreads();

    const int    e0 = blockIdx.x * 1024 + 4 * t;
    const float2 p  = s_phase[t >> 6];

    float v[4];
#pragma unroll
    for (int j = 0; j < 4; ++j) {
        const int e = e0 + j;
        v[j] = 0.0f;
        if (e < x_elems) {
            if (xbf) v[j] = __bfloat162float(((const __nv_bfloat16*)xraw)[e]);
            else     v[j] = ((const float*)xraw)[e];
        }
    }
    if (interleaved) {
#pragma unroll
        for (int j = 0; j < 4; ++j) {
            const int idx = 2 * (e0 + j);
            if (idx + 1 < n_out_floats) {
                outf[idx]     = p.x * v[j];
                outf[idx + 1] = p.y * v[j];
            }
        }
    } else {
#pragma unroll
        for (int j = 0; j < 4; ++j)
            if (e0 + j < n_out_floats) outf[e0 + j] = p.x * v[j];
    }
}

extern "C" void kernel_launch(void* const* d_in, const int* in_sizes, int n_in,
                              void* d_out, int out_size)
{
    // Identify inputs: x = largest, angle = sized 12/24/48.
    int ix = -1, ia = -1;
    for (int i = 0; i < n_in; ++i) {
        const int sz = in_sizes[i];
        if (sz == 12 || sz == 24 || sz == 48) ia = i;
        else if (ix < 0 || sz > in_sizes[ix]) ix = i;
    }
    if (ix < 0) return;
    if (ia < 0) ia = (n_in > 1) ? 1 : ix;

    const void* x = d_in[ix];
    const void* a = d_in[ia];

    int a_hint = -1;
    if (in_sizes[ia] == 48) a_hint = 0;
    else if (in_sizes[ia] == 24) a_hint = 1;
    int x_hint = (in_sizes[ix] == 4 * NELEMS) ? 0 : -1;

    int x_elems = in_sizes[ix];
    if (x_elems > NELEMS) x_elems = NELEMS;

    int interleaved, n_out_floats;
    if (out_size >= 2 * NELEMS)  { interleaved = 1; n_out_floats = 2 * NELEMS; }
    else if (out_size >= NELEMS) { interleaved = 0; n_out_floats = NELEMS; }
    else { interleaved = 0; n_out_floats = out_size > 0 ? out_size : 0; }

    // Validated-ABI fast path (alignment handled INSIDE rz_main per pointer).
    if (interleaved && x_elems == NELEMS && a_hint != 1) {
        const int xv4 = (((uintptr_t)x     & 15u) == 0);
        const int ov4 = (((uintptr_t)d_out & 15u) == 0);
        const int ov2 = (((uintptr_t)d_out & 7u)  == 0);
        rz_main<<<NELEMS / 2048, 256>>>((const float*)x, (const float*)a,
                                        (float*)d_out, xv4, ov4, ov2);
    } else {
        rz_safe<<<NELEMS / 1024, 256>>>(x, x_elems, a,
                                        (float*)d_out, n_out_floats,
                                        interleaved, x_hint, a_hint);
    }
}

// round 10
// speedup vs baseline: 1.0613x; 1.0613x over previous
#include <cuda_runtime.h>
#include <cuda_bf16.h>
#include <stdint.h>

// RZGate, L=12, D=2, J=1.  S = diag(1,-1) => U is DIAGONAL with
//   theta(row) = -0.5 * sum_i a_i * (bit_i(row) ? -1 : +1)   (site 0 = MSB)
//
// TRUE ABI (established round 9): __output__ is FLOAT32 (the jsonl cast of
// the complex64 reference takes the REAL part), out_size == NELEMS:
//   out[row,b] = cos(theta(row)) * x[row,b]        (4 MB)
// Inputs: x f32[4096*256], angle f32[12], S unused (deterministic).
// Rounds 3-5 IMAs were 8 MB writes into this 4 MB buffer (OOB), NOT
// misalignment; alignment is still unverified, so vector widths are chosen
// per-pointer at runtime.

#define LQ      12
#define NROWS   4096
#define NBATCH  256
#define NELEMS  (NROWS * NBATCH)   // 1,048,576

// ---------------------------------------------------------------------------
// FAST kernel: warp == row, 8 floats/lane. 512 blocks x 256 threads.
// Phase: lane-parallel angle*sign + shfl_xor reduce, one cosf per warp.
// Loads/stores float4 when the (runtime) flags allow, else scalar.
// ---------------------------------------------------------------------------
__global__ void __launch_bounds__(256)
rz_real(const float* __restrict__ x,
        const float* __restrict__ ang,
        float*       __restrict__ out,
        int xv4, int ov4)
{
    const int lane = threadIdx.x & 31;
    const int row  = (blockIdx.x * blockDim.x + threadIdx.x) >> 5;  // 0..4095

    // --- per-row phase ---
    float term = 0.0f;
    if (lane < LQ) {
        const int bit = (row >> (LQ - 1 - lane)) & 1;
        term = ang[lane] * (bit ? -1.0f : 1.0f);
    }
#pragma unroll
    for (int o = 16; o; o >>= 1)
        term += __shfl_xor_sync(0xFFFFFFFFu, term, o);

    float cs = 0.0f;
    if (lane == 0) cs = cosf(-0.5f * term);
    cs = __shfl_sync(0xFFFFFFFFu, cs, 0);

    // --- stream 8 consecutive elements of this row per lane ---
    const int e0 = row * NBATCH + lane * 8;

    float v[8];
    if (xv4) {
        const float4* __restrict__ x4 = (const float4*)x;
        const float4 a = x4[(e0 >> 2) + 0];
        const float4 b = x4[(e0 >> 2) + 1];
        v[0] = a.x; v[1] = a.y; v[2] = a.z; v[3] = a.w;
        v[4] = b.x; v[5] = b.y; v[6] = b.z; v[7] = b.w;
    } else {
#pragma unroll
        for (int j = 0; j < 8; ++j) v[j] = __ldg(&x[e0 + j]);
    }

    if (ov4) {
        float4* __restrict__ o4 = (float4*)(out + e0);
        o4[0] = make_float4(cs * v[0], cs * v[1], cs * v[2], cs * v[3]);
        o4[1] = make_float4(cs * v[4], cs * v[5], cs * v[6], cs * v[7]);
    } else {
#pragma unroll
        for (int j = 0; j < 8; ++j) out[e0 + j] = cs * v[j];
    }
}

// ---------------------------------------------------------------------------
// SAFE fallback: all-scalar, dtype-probing, bounds-clamped (proven passing).
// Handles real-only OR interleaved output per host flag.
// ---------------------------------------------------------------------------
__global__ void __launch_bounds__(256)
rz_safe(const void* __restrict__ xraw, int x_elems,
        const void* __restrict__ araw,
        float* __restrict__ outf, int n_out_floats,
        int interleaved, int x_hint, int a_hint)
{
    __shared__ float2 s_phase[4];
    __shared__ int    s_xbf;
    const int t = threadIdx.x;

    if (t == 0) {
        int xbf = x_hint;
        if (xbf < 0) {
            const unsigned short* h = (const unsigned short*)xraw;
            int match = 0;
            for (int i = 0; i < 32; ++i) {
                const int e = (h[2 * i] >> 7) & 0xFF;
                if (e >= 117 && e <= 132) ++match;
            }
            xbf = (match >= 24) ? 1 : 0;
        }
        s_xbf = xbf;
    }
    __syncthreads();
    const int xbf = s_xbf;

    if (t < 4) {
        const int abf = (a_hint >= 0) ? a_hint : xbf;
        const int row = 4 * blockIdx.x + t;
        float th = 0.0f;
#pragma unroll
        for (int i = 0; i < LQ; ++i) {
            float a;
            if (abf) a = __bfloat162float(((const __nv_bfloat16*)araw)[i]);
            else     a = ((const float*)araw)[i];
            const int bit = (row >> (LQ - 1 - i)) & 1;
            th = fmaf(a, bit ? -1.0f : 1.0f, th);
        }
        th *= -0.5f;
        float sc, cc;
        sincosf(th, &sc, &cc);
        s_phase[t] = make_float2(cc, sc);
    }
    __syncthreads();

    const int    e0 = blockIdx.x * 1024 + 4 * t;
    const float2 p  = s_phase[t >> 6];

    float v[4];
#pragma unroll
    for (int j = 0; j < 4; ++j) {
        const int e = e0 + j;
        v[j] = 0.0f;
        if (e < x_elems) {
            if (xbf) v[j] = __bfloat162float(((const __nv_bfloat16*)xraw)[e]);
            else     v[j] = ((const float*)xraw)[e];
        }
    }
    if (interleaved) {
#pragma unroll
        for (int j = 0; j < 4; ++j) {
            const int idx = 2 * (e0 + j);
            if (idx + 1 < n_out_floats) {
                outf[idx]     = p.x * v[j];
                outf[idx + 1] = p.y * v[j];
            }
        }
    } else {
#pragma unroll
        for (int j = 0; j < 4; ++j)
            if (e0 + j < n_out_floats) outf[e0 + j] = p.x * v[j];
    }
}

extern "C" void kernel_launch(void* const* d_in, const int* in_sizes, int n_in,
                              void* d_out, int out_size)
{
    // Identify inputs: x = largest, angle = sized 12/24/48.
    int ix = -1, ia = -1;
    for (int i = 0; i < n_in; ++i) {
        const int sz = in_sizes[i];
        if (sz == 12 || sz == 24 || sz == 48) ia = i;
        else if (ix < 0 || sz > in_sizes[ix]) ix = i;
    }
    if (ix < 0) return;
    if (ia < 0) ia = (n_in > 1) ? 1 : ix;

    const void* x = d_in[ix];
    const void* a = d_in[ia];

    int a_hint = -1;
    if (in_sizes[ia] == 48) a_hint = 0;
    else if (in_sizes[ia] == 24) a_hint = 1;
    int x_hint = (in_sizes[ix] == 4 * NELEMS) ? 0 : -1;

    int x_elems = in_sizes[ix];
    if (x_elems > NELEMS) x_elems = NELEMS;

    // Output convention (round 9 ground truth): out_size == NELEMS float32.
    // Keep interleaved handling only as a never-expected fallback.
    int interleaved, n_out_floats;
    if (out_size >= 2 * NELEMS)  { interleaved = 1; n_out_floats = 2 * NELEMS; }
    else if (out_size >= NELEMS) { interleaved = 0; n_out_floats = NELEMS; }
    else { interleaved = 0; n_out_floats = out_size > 0 ? out_size : 0; }

    const bool fast_ok = !interleaved && n_out_floats == NELEMS &&
                         x_elems == NELEMS && a_hint != 1;

    if (fast_ok) {
        const int xv4 = (((uintptr_t)x     & 15u) == 0);
        const int ov4 = (((uintptr_t)d_out & 15u) == 0);
        rz_real<<<NELEMS / 2048, 256>>>((const float*)x, (const float*)a,
                                        (float*)d_out, xv4, ov4);
    } else {
        rz_safe<<<NELEMS / 1024, 256>>>(x, x_elems, a,
                                        (float*)d_out, n_out_floats,
                                        interleaved, x_hint, a_hint);
    }
}